// round 5
// baseline (speedup 1.0000x reference)
#include <cuda_runtime.h>
#include <cstdint>

// CenterLoss: mean_i ||x[i] - centers[labels[i]]||^2
// B=16384, C=4000, D=512
// Inputs: x [B*D] f32, labels [B] int32, centers [C*D] f32. Output: scalar f32.

#define B_ROWS 16384
#define C_ROWS 4000
#define D_VEC  128               // 512 floats = 128 float4 per row
#define WARPS_PER_BLOCK 8
#define THREADS (WARPS_PER_BLOCK * 32)
#define ROWS_PER_WARP 2
#define GRID_BLOCKS (B_ROWS / (WARPS_PER_BLOCK * ROWS_PER_WARP))  // 1024

// Forced LDG.128: asm volatile can't be reordered vs other asm volatile, so
// 16 consecutive emissions = 16 LDG.128 in flight BEFORE any FFMA (true MLP=16).
#define LDG128(dst, ptr)                                                     \
    asm volatile("ld.global.v4.f32 {%0,%1,%2,%3}, [%4];"                     \
                 : "=f"(dst.x), "=f"(dst.y), "=f"(dst.z), "=f"(dst.w)        \
                 : "l"(ptr))

__global__ __launch_bounds__(THREADS)
void center_loss_kernel(const float4* __restrict__ x,
                        const int* __restrict__ labels,
                        const float4* __restrict__ centers,
                        float* __restrict__ out)
{
    const int warp = threadIdx.x >> 5;
    const int lane = threadIdx.x & 31;
    const int row0 = (blockIdx.x * WARPS_PER_BLOCK + warp) * ROWS_PER_WARP;

    // Resolve both center addresses before the batch (address dep off critical path)
    int lab0 = labels[row0];
    int lab1 = labels[row0 + 1];
    lab0 = min(max(lab0, 0), C_ROWS - 1);
    lab1 = min(max(lab1, 0), C_ROWS - 1);

    const float4* xr0 = x       + (size_t)row0 * D_VEC + lane;
    const float4* xr1 = xr0     + D_VEC;
    const float4* cr0 = centers + (size_t)lab0 * D_VEC + lane;
    const float4* cr1 = centers + (size_t)lab1 * D_VEC + lane;

    float4 a0, a1, a2, a3, a4, a5, a6, a7;
    float4 b0, b1, b2, b3, b4, b5, b6, b7;

    // 16 back-to-back LDG.128 — 8 KB in flight per warp, guaranteed in SASS.
    LDG128(a0, xr0);       LDG128(a1, xr0 + 32);
    LDG128(a2, xr0 + 64);  LDG128(a3, xr0 + 96);
    LDG128(a4, xr1);       LDG128(a5, xr1 + 32);
    LDG128(a6, xr1 + 64);  LDG128(a7, xr1 + 96);
    LDG128(b0, cr0);       LDG128(b1, cr0 + 32);
    LDG128(b2, cr0 + 64);  LDG128(b3, cr0 + 96);
    LDG128(b4, cr1);       LDG128(b5, cr1 + 32);
    LDG128(b6, cr1 + 64);  LDG128(b7, cr1 + 96);

    float s = 0.0f;
    float dx, dy, dz, dw;
    #define ACC(a, b)                                                        \
        dx = a.x - b.x; dy = a.y - b.y; dz = a.z - b.z; dw = a.w - b.w;      \
        s += dx*dx + dy*dy + dz*dz + dw*dw;
    ACC(a0, b0) ACC(a1, b1) ACC(a2, b2) ACC(a3, b3)
    ACC(a4, b4) ACC(a5, b5) ACC(a6, b6) ACC(a7, b7)
    #undef ACC

    // warp reduce
    #pragma unroll
    for (int o = 16; o > 0; o >>= 1)
        s += __shfl_xor_sync(0xFFFFFFFFu, s, o);

    __shared__ float warp_sums[WARPS_PER_BLOCK];
    if (lane == 0) warp_sums[warp] = s;
    __syncthreads();

    if (warp == 0) {
        float v = (lane < WARPS_PER_BLOCK) ? warp_sums[lane] : 0.0f;
        #pragma unroll
        for (int o = 4; o > 0; o >>= 1)
            v += __shfl_xor_sync(0xFFFFFFFFu, v, o);
        if (lane == 0)
            atomicAdd(out, v * (1.0f / (float)B_ROWS));
    }
}

extern "C" void kernel_launch(void* const* d_in, const int* in_sizes, int n_in,
                              void* d_out, int out_size)
{
    const float4* x       = (const float4*)d_in[0];
    const int*    labels  = (const int*)d_in[1];
    const float4* centers = (const float4*)d_in[2];
    float*        out     = (float*)d_out;

    cudaMemsetAsync(out, 0, sizeof(float));
    center_loss_kernel<<<GRID_BLOCKS, THREADS>>>(x, labels, centers, out);
}

// round 6
// speedup vs baseline: 1.0979x; 1.0979x over previous
#include <cuda_runtime.h>
#include <cstdint>

// CenterLoss: mean_i ||x[i] - centers[labels[i]]||^2
// B=16384, C=4000, D=512
// Inputs: x [B*D] f32, labels [B] int32, centers [C*D] f32. Output: scalar f32.
//
// Flat streaming formulation: 16384*128 = 2,097,152 float4-pairs.
// 1024 blocks x 256 threads x 8 grid-strided iterations, continuous load issue.

#define B_ROWS   16384
#define C_ROWS   4000
#define D_VEC    128                       // float4 per row
#define TOTAL_V4 (B_ROWS * D_VEC)          // 2,097,152
#define THREADS  256
#define BLOCKS   1024
#define STRIDE   (THREADS * BLOCKS)        // 262,144
#define ITERS    (TOTAL_V4 / STRIDE)       // 8 exactly

__global__ __launch_bounds__(THREADS)
void center_loss_kernel(const float4* __restrict__ x,
                        const int* __restrict__ labels,
                        const float4* __restrict__ centers,
                        float* __restrict__ out)
{
    const int t = blockIdx.x * THREADS + threadIdx.x;

    float s = 0.0f;

    #pragma unroll
    for (int k = 0; k < ITERS; k++) {
        const int i   = t + k * STRIDE;    // flat float4 index, warp-coalesced
        const int row = i >> 7;            // /128
        const int col = i & 127;

        int lab = labels[row];             // warp-uniform (128 f4/row, 4 warps/row)
        lab = min(max(lab, 0), C_ROWS - 1);

        const float4 a = x[i];
        const float4 b = centers[(size_t)lab * D_VEC + col];

        const float dx = a.x - b.x;
        const float dy = a.y - b.y;
        const float dz = a.z - b.z;
        const float dw = a.w - b.w;
        s += dx*dx + dy*dy + dz*dz + dw*dw;
    }

    // One tail per thread-lifetime instead of one per row: warp reduce,
    // then block reduce, then a single atomic per block (1024 total).
    const int warp = threadIdx.x >> 5;
    const int lane = threadIdx.x & 31;

    #pragma unroll
    for (int o = 16; o > 0; o >>= 1)
        s += __shfl_xor_sync(0xFFFFFFFFu, s, o);

    __shared__ float warp_sums[THREADS / 32];
    if (lane == 0) warp_sums[warp] = s;
    __syncthreads();

    if (warp == 0) {
        float v = (lane < THREADS / 32) ? warp_sums[lane] : 0.0f;
        #pragma unroll
        for (int o = 4; o > 0; o >>= 1)
            v += __shfl_xor_sync(0xFFFFFFFFu, v, o);
        if (lane == 0)
            atomicAdd(out, v * (1.0f / (float)B_ROWS));
    }
}

extern "C" void kernel_launch(void* const* d_in, const int* in_sizes, int n_in,
                              void* d_out, int out_size)
{
    const float4* x       = (const float4*)d_in[0];
    const int*    labels  = (const int*)d_in[1];
    const float4* centers = (const float4*)d_in[2];
    float*        out     = (float*)d_out;

    cudaMemsetAsync(out, 0, sizeof(float));
    center_loss_kernel<<<BLOCKS, THREADS>>>(x, labels, centers, out);
}